// round 13
// baseline (speedup 1.0000x reference)
#include <cuda_runtime.h>
#include <math.h>

#define BN 512   // batch
#define TT 100   // time steps / cities
#define HH 128   // hidden
#define EE 128   // embedding
#define DD 256   // 2*H
#define G4 512   // 4*H
#define NCTA 128 // persistent grid size (single wave: < 148 SMs)

// ---------------- scratch (device globals; no allocation allowed) -------------
__device__ __align__(128) float g_embT[TT * BN * EE];   // [t][b][e]
__device__ __align__(128) float g_enc [BN * TT * DD];   // [b][t][d]
__device__ __align__(128) float g_ref [BN * TT * DD];   // [b][t][d]
__device__ __align__(128) float g_hf  [2 * BN * HH];    // fwd h, parity double buffer
__device__ __align__(128) float g_hb  [2 * BN * HH];    // bwd h
__device__ __align__(128) float g_cf  [BN * HH];
__device__ __align__(128) float g_cb  [BN * HH];
__device__ __align__(128) float g_Wef [G4 * 256];       // [Wih_f | Whh_f] packed
__device__ __align__(128) float g_Web [G4 * 256];
__device__ __align__(128) float g_Wpf [G4 * 384];       // [proc_Wih_f | proc_Whh_f]
__device__ __align__(128) float g_Wpb [G4 * 384];
__device__ __align__(128) float g_pin [BN * DD];
__device__ __align__(128) float g_pout[BN * DD];
__device__ __align__(128) float g_q   [BN * DD];

__device__ unsigned g_bar_sense;   // persists across launches/replays; re-seeded at entry
__device__ unsigned g_bar_count;   // self-resetting (every launch leaves it at 0)

// ---------------- fast activations (MUFU-based, clamped) ----------------------
__device__ __forceinline__ float ftanh(float x) {
    x = fminf(fmaxf(x, -15.f), 15.f);
    float e = __expf(2.f * x);
    return (e - 1.f) / (e + 1.f);
}
__device__ __forceinline__ float fsig(float x) {
    return 1.f / (1.f + __expf(-x));
}

// CG-selectable float4 load (L2-only when CG: cross-CTA data inside persistent kernel)
template <bool CG>
__device__ __forceinline__ float4 ld4(const float* p) {
    if (CG) return __ldcg(reinterpret_cast<const float4*>(p));
    return *reinterpret_cast<const float4*>(p);
}

// ---------------- grid-wide barrier (sense reversal, release/acquire) ---------
__device__ __forceinline__ void grid_bar(unsigned* s_sense) {
    __threadfence();                       // release all my stores at device scope
    __syncthreads();                       // whole block fenced before arrival
    if (threadIdx.x == 0) {
        unsigned s = *s_sense ^ 1u;
        *s_sense = s;
        if (atomicAdd(&g_bar_count, 1u) == NCTA - 1u) {
            g_bar_count = 0u;              // safe: others spin on sense, can't re-arrive
            __threadfence();
            atomicExch(&g_bar_sense, s);   // publish
        } else {
            while (atomicAdd(&g_bar_sense, 0u) != s) __nanosleep(64);
        }
        __threadfence();                   // acquire
    }
    __syncthreads();
}

// ---------------- pack weights + zero-init state ------------------------------
__global__ void pack_kernel(const float* __restrict__ eWihF, const float* __restrict__ eWhhF,
                            const float* __restrict__ eWihB, const float* __restrict__ eWhhB,
                            const float* __restrict__ pWihF, const float* __restrict__ pWhhF,
                            const float* __restrict__ pWihB, const float* __restrict__ pWhhB) {
    int n = blockIdx.x;            // 512 blocks: gate row; reused as batch row for zeroing
    int tid = threadIdx.x;         // 256 threads
    for (int k = tid; k < 256; k += 256) {
        g_Wef[n * 256 + k] = (k < 128) ? eWihF[n * 128 + k] : eWhhF[n * 128 + k - 128];
        g_Web[n * 256 + k] = (k < 128) ? eWihB[n * 128 + k] : eWhhB[n * 128 + k - 128];
    }
    for (int k = tid; k < 384; k += 256) {
        g_Wpf[n * 384 + k] = (k < 256) ? pWihF[n * 256 + k] : pWhhF[n * 128 + k - 256];
        g_Wpb[n * 384 + k] = (k < 256) ? pWihB[n * 256 + k] : pWhhB[n * 128 + k - 256];
    }
    if (tid < 128) {               // zero parity-0 h and c (n = batch row here)
        g_hf[n * HH + tid] = 0.f;
        g_hb[n * HH + tid] = 0.f;
        g_cf[n * HH + tid] = 0.f;
        g_cb[n * HH + tid] = 0.f;
    }
    g_pin[n * DD + tid] = 0.f;     // tid covers 0..255
}

// ---------------- embedding: embT[t][b][e] = inputs[b][t][:] . W_embed[e][:] --
__global__ void embed_kernel(const float* __restrict__ inp, const float* __restrict__ We) {
    int idx = blockIdx.x * 256 + threadIdx.x;   // total = TT*BN*EE = 6,553,600 exactly
    int e = idx & 127;
    int b = (idx >> 7) & 511;
    int t = idx >> 16;
    float x0 = inp[(b * TT + t) * 2 + 0];
    float x1 = inp[(b * TT + t) * 2 + 1];
    g_embT[(t * BN + b) * EE + e] = x0 * We[e * 2 + 0] + x1 * We[e * 2 + 1];
}

// ---------------- fused LSTM-step tile: GEMM + gate nonlinearity --------------
// 32 batch rows x 32 hidden cols, gathered across ALL 4 gate groups, epilogue
// applies the full cell update. gates = [x | hprev] @ W.T + bias.
// CGX/CGH: load x / hprev L2-only (cross-CTA-rewritten data in persistent kernels).
template <int KXW, bool CGX, bool CGH>
__device__ __forceinline__ void lstm_tile(
    int m0, int j0,
    const float* __restrict__ x,      // [BN][KXW]
    const float* __restrict__ hprev,  // [BN][128]
    const float* __restrict__ W,      // [512][KXW+128] packed
    const float* __restrict__ bias,   // [512] (i,f,g,o blocks of 128)
    float* __restrict__ c,            // [BN][128] in-place (same-thread private)
    float* __restrict__ hnext,        // [BN][128]
    float* __restrict__ out2,         // secondary h write (enc slot or pout)
    int out2_stride, int out2_col0)
{
    constexpr int KT = KXW + 128;
    constexpr int NC = KT / 32;
    __shared__ __align__(16) float sA[32][36];      // sA[k][m]
    __shared__ __align__(16) float sW[128][33];     // sW[g*32+jj][k]

    int tid = threadIdx.x;
    int jj = tid & 31;                // hidden col within tile
    int my = tid >> 5;                // warp id -> 4-row group

    float acc[4][4];                  // [row r][gate g]
#pragma unroll
    for (int r = 0; r < 4; r++)
#pragma unroll
        for (int g = 0; g < 4; g++) acc[r][g] = 0.f;

    int arow = tid >> 3;              // 0..31
    int akq  = (tid & 7) * 4;         // 0,4,...,28
    int wr   = tid >> 1;              // 0..127 gathered weight row
    int wn   = ((wr >> 5) * 128) + j0 + (wr & 31);
    int wkh  = (tid & 1) * 16;

#pragma unroll 1
    for (int cc0 = 0; cc0 < NC; cc0++) {
        int k0 = cc0 * 32;
        float4 av;
        if (k0 < KXW) av = ld4<CGX>(x     + (m0 + arow) * KXW + k0 + akq);
        else          av = ld4<CGH>(hprev + (m0 + arow) * 128 + (k0 - KXW) + akq);
        const float* wp = W + wn * KT + k0 + wkh;
        float4 w0 = ld4<false>(wp + 0);
        float4 w1 = ld4<false>(wp + 4);
        float4 w2 = ld4<false>(wp + 8);
        float4 w3 = ld4<false>(wp + 12);

        sA[akq + 0][arow] = av.x; sA[akq + 1][arow] = av.y;
        sA[akq + 2][arow] = av.z; sA[akq + 3][arow] = av.w;
        sW[wr][wkh + 0]  = w0.x; sW[wr][wkh + 1]  = w0.y;
        sW[wr][wkh + 2]  = w0.z; sW[wr][wkh + 3]  = w0.w;
        sW[wr][wkh + 4]  = w1.x; sW[wr][wkh + 5]  = w1.y;
        sW[wr][wkh + 6]  = w1.z; sW[wr][wkh + 7]  = w1.w;
        sW[wr][wkh + 8]  = w2.x; sW[wr][wkh + 9]  = w2.y;
        sW[wr][wkh + 10] = w2.z; sW[wr][wkh + 11] = w2.w;
        sW[wr][wkh + 12] = w3.x; sW[wr][wkh + 13] = w3.y;
        sW[wr][wkh + 14] = w3.z; sW[wr][wkh + 15] = w3.w;
        __syncthreads();

#pragma unroll
        for (int k = 0; k < 32; k++) {
            float4 a = *reinterpret_cast<const float4*>(&sA[k][my * 4]);  // broadcast
            float wi = sW[      jj][k];
            float wf = sW[ 32 + jj][k];
            float wg = sW[ 64 + jj][k];
            float wo = sW[ 96 + jj][k];
            acc[0][0] += a.x * wi; acc[0][1] += a.x * wf; acc[0][2] += a.x * wg; acc[0][3] += a.x * wo;
            acc[1][0] += a.y * wi; acc[1][1] += a.y * wf; acc[1][2] += a.y * wg; acc[1][3] += a.y * wo;
            acc[2][0] += a.z * wi; acc[2][1] += a.z * wf; acc[2][2] += a.z * wg; acc[2][3] += a.z * wo;
            acc[3][0] += a.w * wi; acc[3][1] += a.w * wf; acc[3][2] += a.w * wg; acc[3][3] += a.w * wo;
        }
        __syncthreads();
    }

    // epilogue: LSTM cell update (PyTorch gate order i,f,g,o)
    int j = j0 + jj;
    float bi = bias[j], bf = bias[128 + j], bg = bias[256 + j], bo = bias[384 + j];
#pragma unroll
    for (int r = 0; r < 4; r++) {
        int m = m0 + my * 4 + r;
        float ig = acc[r][0] + bi;
        float fg = acc[r][1] + bf;
        float gg = acc[r][2] + bg;
        float og = acc[r][3] + bo;
        float cold = c[m * HH + j];
        float cn = fsig(fg) * cold + fsig(ig) * ftanh(gg);
        float hn = fsig(og) * ftanh(cn);
        c[m * HH + j]     = cn;
        hnext[m * HH + j] = hn;
        out2[m * out2_stride + out2_col0 + j] = hn;
    }
}

// ---------------- persistent encoder: 100 fused bidirectional LSTM steps ------
// 128 CTAs (2 dir x 4 j-tiles x 16 m-tiles), 99 grid barriers between steps.
__global__ void __launch_bounds__(256) enc_loop_kernel(
        const float* __restrict__ ebf, const float* __restrict__ ebb) {
    __shared__ unsigned s_sense;
    int tid = threadIdx.x;
    int cta = blockIdx.x;
    if (tid == 0) s_sense = g_bar_sense;   // pre-flip seed: replay-safe
    __syncthreads();

    int dir = cta >> 6;                  // 0..1
    int j0  = ((cta >> 4) & 3) * 32;
    int m0  = (cta & 15) * 32;
    float*       hbase = dir ? g_hb : g_hf;
    float*       c     = dir ? g_cb : g_cf;
    const float* W     = dir ? g_Web : g_Wef;
    const float* bias  = dir ? ebb : ebf;

#pragma unroll 1
    for (int t = 0; t < TT; t++) {
        int tt  = dir ? (TT - 1 - t) : t;
        int par = t & 1;
        lstm_tile<128, false, true>(m0, j0,
            g_embT + tt * BN * EE, hbase + par * BN * HH, W, bias,
            c, hbase + (par ^ 1) * BN * HH, g_enc, TT * DD, tt * DD + dir * HH);
        if (t < TT - 1) grid_bar(&s_sense);   // last step: kernel boundary orders
    }
}

// ---------------- ref GEMM: g_ref[m][n] = sum_k g_enc[m][k] * W_ref[n][k] -----
__global__ void __launch_bounds__(256) refgemm_kernel(const float* __restrict__ Wt) {
    const float* A = g_enc;
    float*       C = g_ref;
    __shared__ __align__(16) float sA[16][68];
    __shared__ __align__(16) float sB[16][68];
    int tid = threadIdx.x;
    int tx = tid & 15, ty = tid >> 4;
    int m0 = blockIdx.x * 64, n0 = blockIdx.y * 64;
    float acc[4][4] = {};
    int lrow = tid >> 2;        // 0..63
    int lk   = (tid & 3) * 4;   // 0,4,8,12
#pragma unroll 1
    for (int k0 = 0; k0 < 256; k0 += 16) {
        float4 a = *reinterpret_cast<const float4*>(A  + (m0 + lrow) * 256 + k0 + lk);
        float4 b = *reinterpret_cast<const float4*>(Wt + (n0 + lrow) * 256 + k0 + lk);
        sA[lk + 0][lrow] = a.x; sA[lk + 1][lrow] = a.y; sA[lk + 2][lrow] = a.z; sA[lk + 3][lrow] = a.w;
        sB[lk + 0][lrow] = b.x; sB[lk + 1][lrow] = b.y; sB[lk + 2][lrow] = b.z; sB[lk + 3][lrow] = b.w;
        __syncthreads();
#pragma unroll
        for (int k = 0; k < 16; k++) {
            float4 av = *reinterpret_cast<const float4*>(&sA[k][ty * 4]);
            float4 bv = *reinterpret_cast<const float4*>(&sB[k][tx * 4]);
            acc[0][0] += av.x * bv.x; acc[0][1] += av.x * bv.y; acc[0][2] += av.x * bv.z; acc[0][3] += av.x * bv.w;
            acc[1][0] += av.y * bv.x; acc[1][1] += av.y * bv.y; acc[1][2] += av.y * bv.z; acc[1][3] += av.y * bv.w;
            acc[2][0] += av.z * bv.x; acc[2][1] += av.z * bv.y; acc[2][2] += av.z * bv.z; acc[2][3] += av.z * bv.w;
            acc[3][0] += av.w * bv.x; acc[3][1] += av.w * bv.y; acc[3][2] += av.w * bv.z; acc[3][3] += av.w * bv.w;
        }
        __syncthreads();
    }
#pragma unroll
    for (int r = 0; r < 4; r++) {
        float4 o = make_float4(acc[r][0], acc[r][1], acc[r][2], acc[r][3]);
        *reinterpret_cast<float4*>(C + (m0 + ty * 4 + r) * 256 + n0 + tx * 4) = o;
    }
}

// ---------------- persistent process loop: cell -> q GEMM -> attention --------
// 128 CTAs x 256 threads, single wave. 3 grid barriers per iteration,
// last iteration breaks after the cell (only pout is needed by the head).
__global__ void __launch_bounds__(256) proc_loop_kernel(
        const float* __restrict__ pbf, const float* __restrict__ pbb,
        const float* __restrict__ Wq,  const float* __restrict__ vw) {
    __shared__ unsigned s_sense;
    __shared__ __align__(16) float qA[16][33];
    __shared__ __align__(16) float qB[16][33];
    __shared__ float sq[DD], sv[DD], sc[128];
    __shared__ float s_inv;

    int tid = threadIdx.x;
    int cta = blockIdx.x;
    if (tid == 0) s_sense = g_bar_sense;   // pre-flip seed: replay-safe
    sv[tid] = vw[tid];                     // invariant: loaded once per launch
    __syncthreads();

    // fixed phase-A tile ownership
    int dirA = cta >> 6;                 // 0..1
    int j0A  = ((cta >> 4) & 3) * 32;
    int m0A  = (cta & 15) * 32;
    float*       hbase = dirA ? g_hb : g_hf;
    float*       cA    = dirA ? g_cb : g_cf;
    const float* WA    = dirA ? g_Wpb : g_Wpf;
    const float* biasA = dirA ? pbb : pbf;

    // fixed phase-B tile: 16 m-tiles x 8 n-tiles = 128
    int m0B = (cta & 15) * 32;
    int n0B = (cta >> 4) * 32;
    int txB = tid & 15, tyB = tid >> 4;  // 16x16, 2x2 outputs each
    int lrB = tid & 31;                  // row within 32
    int lkB = (tid >> 5) * 2;            // k-pair base 0..14

    int lane = tid & 31, w = tid >> 5;

#pragma unroll 1
    for (int it = 0; it < TT; it++) {
        // ---- phase A: bidirectional cell (pin, h -> h', c', pout) ----
        {
            int par = it & 1;
            const float* hprev = hbase + par * BN * HH;
            float*       hnext = hbase + (par ^ 1) * BN * HH;
            lstm_tile<256, true, true>(m0A, j0A, g_pin, hprev, WA, biasA,
                                       cA, hnext, g_pout, DD, dirA * HH);
        }
        if (it == TT - 1) break;         // pouts[-1] done; head reads after kernel end
        grid_bar(&s_sense);

        // ---- phase B: q = pout @ Wq.T  (32x32 tile per CTA, K=256) ----
        {
            float a00 = 0.f, a01 = 0.f, a10 = 0.f, a11 = 0.f;
#pragma unroll 1
            for (int k0 = 0; k0 < 256; k0 += 16) {
                float2 av = __ldcg(reinterpret_cast<const float2*>(
                                   &g_pout[(m0B + lrB) * 256 + k0 + lkB]));
                float2 bv = *reinterpret_cast<const float2*>(
                                   &Wq[(n0B + lrB) * 256 + k0 + lkB]);
                qA[lkB + 0][lrB] = av.x; qA[lkB + 1][lrB] = av.y;
                qB[lkB + 0][lrB] = bv.x; qB[lkB + 1][lrB] = bv.y;
                __syncthreads();
#pragma unroll
                for (int k = 0; k < 16; k++) {
                    float am0 = qA[k][tyB * 2], am1 = qA[k][tyB * 2 + 1];
                    float bn0 = qB[k][txB * 2], bn1 = qB[k][txB * 2 + 1];
                    a00 += am0 * bn0; a01 += am0 * bn1;
                    a10 += am1 * bn0; a11 += am1 * bn1;
                }
                __syncthreads();
            }
            g_q[(m0B + tyB * 2)     * 256 + n0B + txB * 2]     = a00;
            g_q[(m0B + tyB * 2)     * 256 + n0B + txB * 2 + 1] = a01;
            g_q[(m0B + tyB * 2 + 1) * 256 + n0B + txB * 2]     = a10;
            g_q[(m0B + tyB * 2 + 1) * 256 + n0B + txB * 2 + 1] = a11;
        }
        grid_bar(&s_sense);

        // ---- phase C: attention for 4 batch rows (v_b dropped: shift-invariant) ----
#pragma unroll 1
        for (int i = 0; i < 4; i++) {
            int b = cta * 4 + i;
            sq[tid] = __ldcg(&g_q[b * DD + tid]);
            __syncthreads();
            for (int t = w; t < TT; t += 8) {
                const float* rr = g_ref + (b * TT + t) * DD;
                float s = 0.f;
#pragma unroll
                for (int u = 0; u < 8; u++) {
                    int d = lane + u * 32;
                    s += sv[d] * ftanh(rr[d] + sq[d]);
                }
#pragma unroll
                for (int o = 16; o; o >>= 1) s += __shfl_xor_sync(0xffffffffu, s, o);
                if (lane == 0) sc[t] = s;
            }
            __syncthreads();
            if (tid < 32) {
                float v0 = (tid      < TT) ? sc[tid]      : -1e30f;
                float v1 = (tid + 32 < TT) ? sc[tid + 32] : -1e30f;
                float v2 = (tid + 64 < TT) ? sc[tid + 64] : -1e30f;
                float v3 = (tid + 96 < TT) ? sc[tid + 96] : -1e30f;
                float mx = fmaxf(fmaxf(v0, v1), fmaxf(v2, v3));
#pragma unroll
                for (int o = 16; o; o >>= 1) mx = fmaxf(mx, __shfl_xor_sync(0xffffffffu, mx, o));
                float e0 = (tid      < TT) ? __expf(v0 - mx) : 0.f;
                float e1 = (tid + 32 < TT) ? __expf(v1 - mx) : 0.f;
                float e2 = (tid + 64 < TT) ? __expf(v2 - mx) : 0.f;
                float e3 = (tid + 96 < TT) ? __expf(v3 - mx) : 0.f;
                if (tid      < TT) sc[tid]      = e0;
                if (tid + 32 < TT) sc[tid + 32] = e1;
                if (tid + 64 < TT) sc[tid + 64] = e2;
                if (tid + 96 < TT) sc[tid + 96] = e3;
                float sum = e0 + e1 + e2 + e3;
#pragma unroll
                for (int o = 16; o; o >>= 1) sum += __shfl_xor_sync(0xffffffffu, sum, o);
                if (tid == 0) s_inv = 1.f / sum;
            }
            __syncthreads();
            float acc = 0.f;
            const float* er = g_enc + b * TT * DD + tid;
#pragma unroll 4
            for (int t = 0; t < TT; t++) acc += sc[t] * er[t * DD];
            g_pin[b * DD + tid] = acc * s_inv;
        }
        grid_bar(&s_sense);
    }
}

// ---------------- final MLP head: out[b] = relu(pout@W1.T+b1)@W2.T + b2 ------
__global__ void __launch_bounds__(256) head_kernel(
        const float* __restrict__ W1, const float* __restrict__ b1,
        const float* __restrict__ W2, const float* __restrict__ b2,
        float* __restrict__ out) {
    int b = blockIdx.x;
    int tid = threadIdx.x, lane = tid & 31, w = tid >> 5;
    __shared__ float sp[DD];
    __shared__ float sh[8];
    sp[tid] = g_pout[b * DD + tid];
    __syncthreads();
    float hv = 0.f;
    if (tid < 100) {   // MID = 100 hidden units
        const float* wr = W1 + tid * DD;
        float s = 0.f;
#pragma unroll 8
        for (int k = 0; k < DD; k++) s += sp[k] * wr[k];
        hv = fmaxf(s + b1[tid], 0.f) * W2[tid];
    }
#pragma unroll
    for (int o = 16; o; o >>= 1) hv += __shfl_xor_sync(0xffffffffu, hv, o);
    if (lane == 0) sh[w] = hv;
    __syncthreads();
    if (tid == 0) {
        float s = 0.f;
#pragma unroll
        for (int i = 0; i < 8; i++) s += sh[i];
        out[b] = s + b2[0];
    }
}

// ---------------- launch ------------------------------------------------------
extern "C" void kernel_launch(void* const* d_in, const int* in_sizes, int n_in,
                              void* d_out, int out_size) {
    (void)in_sizes; (void)n_in; (void)out_size;
    const float* inputs   = (const float*)d_in[0];
    const float* W_embed  = (const float*)d_in[1];
    const float* enc_b_f  = (const float*)d_in[4];
    const float* enc_b_b  = (const float*)d_in[7];
    const float* W_ref    = (const float*)d_in[8];
    const float* W_q      = (const float*)d_in[9];
    const float* v_w      = (const float*)d_in[10];
    const float* proc_b_f = (const float*)d_in[14];
    const float* proc_b_b = (const float*)d_in[17];
    const float* W1       = (const float*)d_in[18];
    const float* b1       = (const float*)d_in[19];
    const float* W2       = (const float*)d_in[20];
    const float* b2       = (const float*)d_in[21];
    float* out = (float*)d_out;

    pack_kernel<<<512, 256>>>((const float*)d_in[2],  (const float*)d_in[3],
                              (const float*)d_in[5],  (const float*)d_in[6],
                              (const float*)d_in[12], (const float*)d_in[13],
                              (const float*)d_in[15], (const float*)d_in[16]);
    embed_kernel<<<(TT * BN * EE) / 256, 256>>>(inputs, W_embed);

    enc_loop_kernel<<<NCTA, 256>>>(enc_b_f, enc_b_b);

    refgemm_kernel<<<dim3((BN * TT) / 64, DD / 64), 256>>>(W_ref);

    proc_loop_kernel<<<NCTA, 256>>>(proc_b_f, proc_b_b, W_q, v_w);

    head_kernel<<<BN, 256>>>(W1, b1, W2, b2, out);
}

// round 14
// speedup vs baseline: 1.0044x; 1.0044x over previous
#include <cuda_runtime.h>
#include <math.h>

#define BN 512   // batch
#define TT 100   // time steps / cities
#define HH 128   // hidden
#define EE 128   // embedding
#define DD 256   // 2*H
#define G4 512   // 4*H
#define NCTA 128 // persistent grid size (single wave: < 148 SMs)

// ---------------- scratch (device globals; no allocation allowed) -------------
__device__ __align__(128) float g_embT[TT * BN * EE];   // [t][b][e]
__device__ __align__(128) float g_enc [BN * TT * DD];   // [b][t][d]
__device__ __align__(128) float g_ref [BN * TT * DD];   // [b][t][d]
__device__ __align__(128) float g_hf  [2 * BN * HH];    // fwd h, parity double buffer
__device__ __align__(128) float g_hb  [2 * BN * HH];    // bwd h
__device__ __align__(128) float g_cf  [BN * HH];
__device__ __align__(128) float g_cb  [BN * HH];
__device__ __align__(128) float g_Wef [G4 * 256];       // [Wih_f | Whh_f] packed
__device__ __align__(128) float g_Web [G4 * 256];
__device__ __align__(128) float g_Wpf [G4 * 384];       // [proc_Wih_f | proc_Whh_f]
__device__ __align__(128) float g_Wpb [G4 * 384];
__device__ __align__(128) float g_pin [BN * DD];
__device__ __align__(128) float g_pout[BN * DD];
__device__ __align__(128) float g_q   [BN * DD];

__device__ unsigned g_bar_sense;   // persists across launches/replays; re-seeded at entry
__device__ unsigned g_bar_count;   // self-resetting (every launch leaves it at 0)

// ---------------- fast activations (MUFU-based, clamped) ----------------------
__device__ __forceinline__ float ftanh(float x) {
    x = fminf(fmaxf(x, -15.f), 15.f);
    float e = __expf(2.f * x);
    return (e - 1.f) / (e + 1.f);
}
__device__ __forceinline__ float fsig(float x) {
    return 1.f / (1.f + __expf(-x));
}

// CG-selectable float4 load (L2-only when CG: cross-CTA data inside persistent kernel)
template <bool CG>
__device__ __forceinline__ float4 ld4(const float* p) {
    if (CG) return __ldcg(reinterpret_cast<const float4*>(p));
    return *reinterpret_cast<const float4*>(p);
}

// ---------------- acq/rel atomics (NO __threadfence: avoids CCTL.IVALL L1 flush)
__device__ __forceinline__ unsigned ld_acquire_gpu(unsigned* p) {
    unsigned v;
    asm volatile("ld.acquire.gpu.u32 %0, [%1];" : "=r"(v) : "l"(p) : "memory");
    return v;
}
__device__ __forceinline__ unsigned atom_add_acqrel_gpu(unsigned* p, unsigned v) {
    unsigned old;
    asm volatile("atom.add.acq_rel.gpu.u32 %0, [%1], %2;" : "=r"(old) : "l"(p), "r"(v) : "memory");
    return old;
}
__device__ __forceinline__ void st_relaxed_gpu(unsigned* p, unsigned v) {
    asm volatile("st.relaxed.gpu.u32 [%0], %1;" :: "l"(p), "r"(v) : "memory");
}
__device__ __forceinline__ void atom_exch_release_gpu(unsigned* p, unsigned v) {
    unsigned old;
    asm volatile("atom.exch.release.gpu.b32 %0, [%1], %2;" : "=r"(old) : "l"(p), "r"(v) : "memory");
    (void)old;
}

// ---------------- grid-wide barrier (sense reversal, single-thread acq/rel) ---
// __syncthreads (CTA-scope acq_rel) orders the block's stores before thread 0's
// release-arrive; waiters poll with acquire LOADS (no RMW contention); the
// trailing __syncthreads broadcasts the acquire to the whole CTA. Cross-CTA
// payload is always read via __ldcg (L2), so no L1 invalidation is needed.
__device__ __forceinline__ void grid_bar(unsigned* s_sense) {
    __syncthreads();
    if (threadIdx.x == 0) {
        unsigned s = *s_sense ^ 1u;
        *s_sense = s;
        if (atom_add_acqrel_gpu(&g_bar_count, 1u) == NCTA - 1u) {
            st_relaxed_gpu(&g_bar_count, 0u);     // ordered before publish by release
            atom_exch_release_gpu(&g_bar_sense, s);
        } else {
            while (ld_acquire_gpu(&g_bar_sense) != s) __nanosleep(32);
        }
    }
    __syncthreads();
}

// ---------------- pack weights + zero-init state ------------------------------
__global__ void pack_kernel(const float* __restrict__ eWihF, const float* __restrict__ eWhhF,
                            const float* __restrict__ eWihB, const float* __restrict__ eWhhB,
                            const float* __restrict__ pWihF, const float* __restrict__ pWhhF,
                            const float* __restrict__ pWihB, const float* __restrict__ pWhhB) {
    int n = blockIdx.x;            // 512 blocks: gate row; reused as batch row for zeroing
    int tid = threadIdx.x;         // 256 threads
    for (int k = tid; k < 256; k += 256) {
        g_Wef[n * 256 + k] = (k < 128) ? eWihF[n * 128 + k] : eWhhF[n * 128 + k - 128];
        g_Web[n * 256 + k] = (k < 128) ? eWihB[n * 128 + k] : eWhhB[n * 128 + k - 128];
    }
    for (int k = tid; k < 384; k += 256) {
        g_Wpf[n * 384 + k] = (k < 256) ? pWihF[n * 256 + k] : pWhhF[n * 128 + k - 256];
        g_Wpb[n * 384 + k] = (k < 256) ? pWihB[n * 256 + k] : pWhhB[n * 128 + k - 256];
    }
    if (tid < 128) {               // zero parity-0 h and c (n = batch row here)
        g_hf[n * HH + tid] = 0.f;
        g_hb[n * HH + tid] = 0.f;
        g_cf[n * HH + tid] = 0.f;
        g_cb[n * HH + tid] = 0.f;
    }
    g_pin[n * DD + tid] = 0.f;     // tid covers 0..255
}

// ---------------- embedding: embT[t][b][e] = inputs[b][t][:] . W_embed[e][:] --
__global__ void embed_kernel(const float* __restrict__ inp, const float* __restrict__ We) {
    int idx = blockIdx.x * 256 + threadIdx.x;   // total = TT*BN*EE = 6,553,600 exactly
    int e = idx & 127;
    int b = (idx >> 7) & 511;
    int t = idx >> 16;
    float x0 = inp[(b * TT + t) * 2 + 0];
    float x1 = inp[(b * TT + t) * 2 + 1];
    g_embT[(t * BN + b) * EE + e] = x0 * We[e * 2 + 0] + x1 * We[e * 2 + 1];
}

// ---------------- fused LSTM-step tile: GEMM + gate nonlinearity --------------
// 32 batch rows x 32 hidden cols, gathered across ALL 4 gate groups, epilogue
// applies the full cell update. gates = [x | hprev] @ W.T + bias.
// CGX/CGH: load x / hprev L2-only (cross-CTA-rewritten data in persistent kernels).
template <int KXW, bool CGX, bool CGH>
__device__ __forceinline__ void lstm_tile(
    int m0, int j0,
    const float* __restrict__ x,      // [BN][KXW]
    const float* __restrict__ hprev,  // [BN][128]
    const float* __restrict__ W,      // [512][KXW+128] packed
    const float* __restrict__ bias,   // [512] (i,f,g,o blocks of 128)
    float* __restrict__ c,            // [BN][128] in-place (same-thread private)
    float* __restrict__ hnext,        // [BN][128]
    float* __restrict__ out2,         // secondary h write (enc slot or pout)
    int out2_stride, int out2_col0)
{
    constexpr int KT = KXW + 128;
    constexpr int NC = KT / 32;
    __shared__ __align__(16) float sA[32][36];      // sA[k][m]
    __shared__ __align__(16) float sW[128][33];     // sW[g*32+jj][k]

    int tid = threadIdx.x;
    int jj = tid & 31;                // hidden col within tile
    int my = tid >> 5;                // warp id -> 4-row group

    float acc[4][4];                  // [row r][gate g]
#pragma unroll
    for (int r = 0; r < 4; r++)
#pragma unroll
        for (int g = 0; g < 4; g++) acc[r][g] = 0.f;

    int arow = tid >> 3;              // 0..31
    int akq  = (tid & 7) * 4;         // 0,4,...,28
    int wr   = tid >> 1;              // 0..127 gathered weight row
    int wn   = ((wr >> 5) * 128) + j0 + (wr & 31);
    int wkh  = (tid & 1) * 16;

#pragma unroll 1
    for (int cc0 = 0; cc0 < NC; cc0++) {
        int k0 = cc0 * 32;
        float4 av;
        if (k0 < KXW) av = ld4<CGX>(x     + (m0 + arow) * KXW + k0 + akq);
        else          av = ld4<CGH>(hprev + (m0 + arow) * 128 + (k0 - KXW) + akq);
        const float* wp = W + wn * KT + k0 + wkh;
        float4 w0 = ld4<false>(wp + 0);
        float4 w1 = ld4<false>(wp + 4);
        float4 w2 = ld4<false>(wp + 8);
        float4 w3 = ld4<false>(wp + 12);

        sA[akq + 0][arow] = av.x; sA[akq + 1][arow] = av.y;
        sA[akq + 2][arow] = av.z; sA[akq + 3][arow] = av.w;
        sW[wr][wkh + 0]  = w0.x; sW[wr][wkh + 1]  = w0.y;
        sW[wr][wkh + 2]  = w0.z; sW[wr][wkh + 3]  = w0.w;
        sW[wr][wkh + 4]  = w1.x; sW[wr][wkh + 5]  = w1.y;
        sW[wr][wkh + 6]  = w1.z; sW[wr][wkh + 7]  = w1.w;
        sW[wr][wkh + 8]  = w2.x; sW[wr][wkh + 9]  = w2.y;
        sW[wr][wkh + 10] = w2.z; sW[wr][wkh + 11] = w2.w;
        sW[wr][wkh + 12] = w3.x; sW[wr][wkh + 13] = w3.y;
        sW[wr][wkh + 14] = w3.z; sW[wr][wkh + 15] = w3.w;
        __syncthreads();

#pragma unroll
        for (int k = 0; k < 32; k++) {
            float4 a = *reinterpret_cast<const float4*>(&sA[k][my * 4]);  // broadcast
            float wi = sW[      jj][k];
            float wf = sW[ 32 + jj][k];
            float wg = sW[ 64 + jj][k];
            float wo = sW[ 96 + jj][k];
            acc[0][0] += a.x * wi; acc[0][1] += a.x * wf; acc[0][2] += a.x * wg; acc[0][3] += a.x * wo;
            acc[1][0] += a.y * wi; acc[1][1] += a.y * wf; acc[1][2] += a.y * wg; acc[1][3] += a.y * wo;
            acc[2][0] += a.z * wi; acc[2][1] += a.z * wf; acc[2][2] += a.z * wg; acc[2][3] += a.z * wo;
            acc[3][0] += a.w * wi; acc[3][1] += a.w * wf; acc[3][2] += a.w * wg; acc[3][3] += a.w * wo;
        }
        __syncthreads();
    }

    // epilogue: LSTM cell update (PyTorch gate order i,f,g,o)
    int j = j0 + jj;
    float bi = bias[j], bf = bias[128 + j], bg = bias[256 + j], bo = bias[384 + j];
#pragma unroll
    for (int r = 0; r < 4; r++) {
        int m = m0 + my * 4 + r;
        float ig = acc[r][0] + bi;
        float fg = acc[r][1] + bf;
        float gg = acc[r][2] + bg;
        float og = acc[r][3] + bo;
        float cold = c[m * HH + j];
        float cn = fsig(fg) * cold + fsig(ig) * ftanh(gg);
        float hn = fsig(og) * ftanh(cn);
        c[m * HH + j]     = cn;
        hnext[m * HH + j] = hn;
        out2[m * out2_stride + out2_col0 + j] = hn;
    }
}

// ---------------- persistent encoder: 100 fused bidirectional LSTM steps ------
// 128 CTAs (2 dir x 4 j-tiles x 16 m-tiles), 99 grid barriers between steps.
__global__ void __launch_bounds__(256) enc_loop_kernel(
        const float* __restrict__ ebf, const float* __restrict__ ebb) {
    __shared__ unsigned s_sense;
    int tid = threadIdx.x;
    int cta = blockIdx.x;
    if (tid == 0) s_sense = g_bar_sense;   // pre-flip seed: replay-safe
    __syncthreads();

    int dir = cta >> 6;                  // 0..1
    int j0  = ((cta >> 4) & 3) * 32;
    int m0  = (cta & 15) * 32;
    float*       hbase = dir ? g_hb : g_hf;
    float*       c     = dir ? g_cb : g_cf;
    const float* W     = dir ? g_Web : g_Wef;
    const float* bias  = dir ? ebb : ebf;

#pragma unroll 1
    for (int t = 0; t < TT; t++) {
        int tt  = dir ? (TT - 1 - t) : t;
        int par = t & 1;
        lstm_tile<128, false, true>(m0, j0,
            g_embT + tt * BN * EE, hbase + par * BN * HH, W, bias,
            c, hbase + (par ^ 1) * BN * HH, g_enc, TT * DD, tt * DD + dir * HH);
        if (t < TT - 1) grid_bar(&s_sense);   // last step: kernel boundary orders
    }
}

// ---------------- ref GEMM: g_ref[m][n] = sum_k g_enc[m][k] * W_ref[n][k] -----
__global__ void __launch_bounds__(256) refgemm_kernel(const float* __restrict__ Wt) {
    const float* A = g_enc;
    float*       C = g_ref;
    __shared__ __align__(16) float sA[16][68];
    __shared__ __align__(16) float sB[16][68];
    int tid = threadIdx.x;
    int tx = tid & 15, ty = tid >> 4;
    int m0 = blockIdx.x * 64, n0 = blockIdx.y * 64;
    float acc[4][4] = {};
    int lrow = tid >> 2;        // 0..63
    int lk   = (tid & 3) * 4;   // 0,4,8,12
#pragma unroll 1
    for (int k0 = 0; k0 < 256; k0 += 16) {
        float4 a = *reinterpret_cast<const float4*>(A  + (m0 + lrow) * 256 + k0 + lk);
        float4 b = *reinterpret_cast<const float4*>(Wt + (n0 + lrow) * 256 + k0 + lk);
        sA[lk + 0][lrow] = a.x; sA[lk + 1][lrow] = a.y; sA[lk + 2][lrow] = a.z; sA[lk + 3][lrow] = a.w;
        sB[lk + 0][lrow] = b.x; sB[lk + 1][lrow] = b.y; sB[lk + 2][lrow] = b.z; sB[lk + 3][lrow] = b.w;
        __syncthreads();
#pragma unroll
        for (int k = 0; k < 16; k++) {
            float4 av = *reinterpret_cast<const float4*>(&sA[k][ty * 4]);
            float4 bv = *reinterpret_cast<const float4*>(&sB[k][tx * 4]);
            acc[0][0] += av.x * bv.x; acc[0][1] += av.x * bv.y; acc[0][2] += av.x * bv.z; acc[0][3] += av.x * bv.w;
            acc[1][0] += av.y * bv.x; acc[1][1] += av.y * bv.y; acc[1][2] += av.y * bv.z; acc[1][3] += av.y * bv.w;
            acc[2][0] += av.z * bv.x; acc[2][1] += av.z * bv.y; acc[2][2] += av.z * bv.z; acc[2][3] += av.z * bv.w;
            acc[3][0] += av.w * bv.x; acc[3][1] += av.w * bv.y; acc[3][2] += av.w * bv.z; acc[3][3] += av.w * bv.w;
        }
        __syncthreads();
    }
#pragma unroll
    for (int r = 0; r < 4; r++) {
        float4 o = make_float4(acc[r][0], acc[r][1], acc[r][2], acc[r][3]);
        *reinterpret_cast<float4*>(C + (m0 + ty * 4 + r) * 256 + n0 + tx * 4) = o;
    }
}

// ---------------- persistent process loop: cell -> q GEMM -> attention --------
// 128 CTAs x 256 threads, single wave. 3 grid barriers per iteration,
// last iteration breaks after the cell (only pout is needed by the head).
__global__ void __launch_bounds__(256) proc_loop_kernel(
        const float* __restrict__ pbf, const float* __restrict__ pbb,
        const float* __restrict__ Wq,  const float* __restrict__ vw) {
    __shared__ unsigned s_sense;
    __shared__ __align__(16) float qA[16][33];
    __shared__ __align__(16) float qB[16][33];
    __shared__ float sq[DD], sv[DD], sc[128];
    __shared__ float s_inv;

    int tid = threadIdx.x;
    int cta = blockIdx.x;
    if (tid == 0) s_sense = g_bar_sense;   // pre-flip seed: replay-safe
    sv[tid] = vw[tid];                     // invariant: loaded once per launch
    __syncthreads();

    // fixed phase-A tile ownership
    int dirA = cta >> 6;                 // 0..1
    int j0A  = ((cta >> 4) & 3) * 32;
    int m0A  = (cta & 15) * 32;
    float*       hbase = dirA ? g_hb : g_hf;
    float*       cA    = dirA ? g_cb : g_cf;
    const float* WA    = dirA ? g_Wpb : g_Wpf;
    const float* biasA = dirA ? pbb : pbf;

    // fixed phase-B tile: 16 m-tiles x 8 n-tiles = 128
    int m0B = (cta & 15) * 32;
    int n0B = (cta >> 4) * 32;
    int txB = tid & 15, tyB = tid >> 4;  // 16x16, 2x2 outputs each
    int lrB = tid & 31;                  // row within 32
    int lkB = (tid >> 5) * 2;            // k-pair base 0..14

    int lane = tid & 31, w = tid >> 5;

#pragma unroll 1
    for (int it = 0; it < TT; it++) {
        // ---- phase A: bidirectional cell (pin, h -> h', c', pout) ----
        {
            int par = it & 1;
            const float* hprev = hbase + par * BN * HH;
            float*       hnext = hbase + (par ^ 1) * BN * HH;
            lstm_tile<256, true, true>(m0A, j0A, g_pin, hprev, WA, biasA,
                                       cA, hnext, g_pout, DD, dirA * HH);
        }
        if (it == TT - 1) break;         // pouts[-1] done; head reads after kernel end
        grid_bar(&s_sense);

        // ---- phase B: q = pout @ Wq.T  (32x32 tile per CTA, K=256) ----
        {
            float a00 = 0.f, a01 = 0.f, a10 = 0.f, a11 = 0.f;
#pragma unroll 1
            for (int k0 = 0; k0 < 256; k0 += 16) {
                float2 av = __ldcg(reinterpret_cast<const float2*>(
                                   &g_pout[(m0B + lrB) * 256 + k0 + lkB]));
                float2 bv = *reinterpret_cast<const float2*>(
                                   &Wq[(n0B + lrB) * 256 + k0 + lkB]);
                qA[lkB + 0][lrB] = av.x; qA[lkB + 1][lrB] = av.y;
                qB[lkB + 0][lrB] = bv.x; qB[lkB + 1][lrB] = bv.y;
                __syncthreads();
#pragma unroll
                for (int k = 0; k < 16; k++) {
                    float am0 = qA[k][tyB * 2], am1 = qA[k][tyB * 2 + 1];
                    float bn0 = qB[k][txB * 2], bn1 = qB[k][txB * 2 + 1];
                    a00 += am0 * bn0; a01 += am0 * bn1;
                    a10 += am1 * bn0; a11 += am1 * bn1;
                }
                __syncthreads();
            }
            g_q[(m0B + tyB * 2)     * 256 + n0B + txB * 2]     = a00;
            g_q[(m0B + tyB * 2)     * 256 + n0B + txB * 2 + 1] = a01;
            g_q[(m0B + tyB * 2 + 1) * 256 + n0B + txB * 2]     = a10;
            g_q[(m0B + tyB * 2 + 1) * 256 + n0B + txB * 2 + 1] = a11;
        }
        grid_bar(&s_sense);

        // ---- phase C: attention for 4 batch rows (v_b dropped: shift-invariant) ----
#pragma unroll 1
        for (int i = 0; i < 4; i++) {
            int b = cta * 4 + i;
            sq[tid] = __ldcg(&g_q[b * DD + tid]);
            __syncthreads();
            for (int t = w; t < TT; t += 8) {
                const float* rr = g_ref + (b * TT + t) * DD;
                float s = 0.f;
#pragma unroll
                for (int u = 0; u < 8; u++) {
                    int d = lane + u * 32;
                    s += sv[d] * ftanh(rr[d] + sq[d]);
                }
#pragma unroll
                for (int o = 16; o; o >>= 1) s += __shfl_xor_sync(0xffffffffu, s, o);
                if (lane == 0) sc[t] = s;
            }
            __syncthreads();
            if (tid < 32) {
                float v0 = (tid      < TT) ? sc[tid]      : -1e30f;
                float v1 = (tid + 32 < TT) ? sc[tid + 32] : -1e30f;
                float v2 = (tid + 64 < TT) ? sc[tid + 64] : -1e30f;
                float v3 = (tid + 96 < TT) ? sc[tid + 96] : -1e30f;
                float mx = fmaxf(fmaxf(v0, v1), fmaxf(v2, v3));
#pragma unroll
                for (int o = 16; o; o >>= 1) mx = fmaxf(mx, __shfl_xor_sync(0xffffffffu, mx, o));
                float e0 = (tid      < TT) ? __expf(v0 - mx) : 0.f;
                float e1 = (tid + 32 < TT) ? __expf(v1 - mx) : 0.f;
                float e2 = (tid + 64 < TT) ? __expf(v2 - mx) : 0.f;
                float e3 = (tid + 96 < TT) ? __expf(v3 - mx) : 0.f;
                if (tid      < TT) sc[tid]      = e0;
                if (tid + 32 < TT) sc[tid + 32] = e1;
                if (tid + 64 < TT) sc[tid + 64] = e2;
                if (tid + 96 < TT) sc[tid + 96] = e3;
                float sum = e0 + e1 + e2 + e3;
#pragma unroll
                for (int o = 16; o; o >>= 1) sum += __shfl_xor_sync(0xffffffffu, sum, o);
                if (tid == 0) s_inv = 1.f / sum;
            }
            __syncthreads();
            float acc = 0.f;
            const float* er = g_enc + b * TT * DD + tid;
#pragma unroll 4
            for (int t = 0; t < TT; t++) acc += sc[t] * er[t * DD];
            g_pin[b * DD + tid] = acc * s_inv;
        }
        grid_bar(&s_sense);
    }
}

// ---------------- final MLP head: out[b] = relu(pout@W1.T+b1)@W2.T + b2 ------
__global__ void __launch_bounds__(256) head_kernel(
        const float* __restrict__ W1, const float* __restrict__ b1,
        const float* __restrict__ W2, const float* __restrict__ b2,
        float* __restrict__ out) {
    int b = blockIdx.x;
    int tid = threadIdx.x, lane = tid & 31, w = tid >> 5;
    __shared__ float sp[DD];
    __shared__ float sh[8];
    sp[tid] = g_pout[b * DD + tid];
    __syncthreads();
    float hv = 0.f;
    if (tid < 100) {   // MID = 100 hidden units
        const float* wr = W1 + tid * DD;
        float s = 0.f;
#pragma unroll 8
        for (int k = 0; k < DD; k++) s += sp[k] * wr[k];
        hv = fmaxf(s + b1[tid], 0.f) * W2[tid];
    }
#pragma unroll
    for (int o = 16; o; o >>= 1) hv += __shfl_xor_sync(0xffffffffu, hv, o);
    if (lane == 0) sh[w] = hv;
    __syncthreads();
    if (tid == 0) {
        float s = 0.f;
#pragma unroll
        for (int i = 0; i < 8; i++) s += sh[i];
        out[b] = s + b2[0];
    }
}

// ---------------- launch ------------------------------------------------------
extern "C" void kernel_launch(void* const* d_in, const int* in_sizes, int n_in,
                              void* d_out, int out_size) {
    (void)in_sizes; (void)n_in; (void)out_size;
    const float* inputs   = (const float*)d_in[0];
    const float* W_embed  = (const float*)d_in[1];
    const float* enc_b_f  = (const float*)d_in[4];
    const float* enc_b_b  = (const float*)d_in[7];
    const float* W_ref    = (const float*)d_in[8];
    const float* W_q      = (const float*)d_in[9];
    const float* v_w      = (const float*)d_in[10];
    const float* proc_b_f = (const float*)d_in[14];
    const float* proc_b_b = (const float*)d_in[17];
    const float* W1       = (const float*)d_in[18];
    const float* b1       = (const float*)d_in[19];
    const float* W2       = (const float*)d_in[20];
    const float* b2       = (const float*)d_in[21];
    float* out = (float*)d_out;

    pack_kernel<<<512, 256>>>((const float*)d_in[2],  (const float*)d_in[3],
                              (const float*)d_in[5],  (const float*)d_in[6],
                              (const float*)d_in[12], (const float*)d_in[13],
                              (const float*)d_in[15], (const float*)d_in[16]);
    embed_kernel<<<(TT * BN * EE) / 256, 256>>>(inputs, W_embed);

    enc_loop_kernel<<<NCTA, 256>>>(enc_b_f, enc_b_b);

    refgemm_kernel<<<dim3((BN * TT) / 64, DD / 64), 256>>>(W_ref);

    proc_loop_kernel<<<NCTA, 256>>>(proc_b_f, proc_b_b, W_q, v_w);

    head_kernel<<<BN, 256>>>(W1, b1, W2, b2, out);
}

// round 17
// speedup vs baseline: 3.5491x; 3.5335x over previous
#include <cuda_runtime.h>
#include <math.h>

#define BN 512   // batch
#define TT 100   // time steps / cities
#define HH 128   // hidden
#define EE 128   // embedding
#define DD 256   // 2*H
#define G4 512   // 4*H

// ---------------- scratch (device globals; no allocation allowed) -------------
__device__ __align__(128) float g_embT[TT * BN * EE];   // [t][b][e]
__device__ __align__(128) float g_enc [BN * TT * DD];   // [b][t][d]
__device__ __align__(128) float g_ref [BN * TT * DD];   // [b][t][d]
__device__ __align__(128) float g_hf  [2 * BN * HH];    // fwd h, parity double buffer
__device__ __align__(128) float g_hb  [2 * BN * HH];    // bwd h
__device__ __align__(128) float g_cf  [BN * HH];
__device__ __align__(128) float g_cb  [BN * HH];
__device__ __align__(128) float g_Wef [G4 * 256];       // [Wih_f | Whh_f] packed
__device__ __align__(128) float g_Web [G4 * 256];
__device__ __align__(128) float g_Wpf [G4 * 384];       // [proc_Wih_f | proc_Whh_f]
__device__ __align__(128) float g_Wpb [G4 * 384];
__device__ __align__(128) float g_pin [BN * DD];
__device__ __align__(128) float g_pout[BN * DD];
__device__ __align__(128) float g_q   [BN * DD];

// ---------------- fast activations (MUFU exp + fast reciprocal) ---------------
__device__ __forceinline__ float ftanh(float x) {
    x = fminf(fmaxf(x, -15.f), 15.f);
    float e = __expf(2.f * x);
    return __fdividef(e - 1.f, e + 1.f);   // div.approx: RCP+mul, no Newton chain
}
__device__ __forceinline__ float fsig(float x) {
    return __fdividef(1.f, 1.f + __expf(-x));
}

// ---------------- pack weights + zero-init state ------------------------------
__global__ void pack_kernel(const float* __restrict__ eWihF, const float* __restrict__ eWhhF,
                            const float* __restrict__ eWihB, const float* __restrict__ eWhhB,
                            const float* __restrict__ pWihF, const float* __restrict__ pWhhF,
                            const float* __restrict__ pWihB, const float* __restrict__ pWhhB) {
    int n = blockIdx.x;            // 512 blocks: gate row; reused as batch row for zeroing
    int tid = threadIdx.x;         // 256 threads
    for (int k = tid; k < 256; k += 256) {
        g_Wef[n * 256 + k] = (k < 128) ? eWihF[n * 128 + k] : eWhhF[n * 128 + k - 128];
        g_Web[n * 256 + k] = (k < 128) ? eWihB[n * 128 + k] : eWhhB[n * 128 + k - 128];
    }
    for (int k = tid; k < 384; k += 256) {
        g_Wpf[n * 384 + k] = (k < 256) ? pWihF[n * 256 + k] : pWhhF[n * 128 + k - 256];
        g_Wpb[n * 384 + k] = (k < 256) ? pWihB[n * 256 + k] : pWhhB[n * 128 + k - 256];
    }
    if (tid < 128) {               // zero parity-0 h and c (n = batch row here)
        g_hf[n * HH + tid] = 0.f;
        g_hb[n * HH + tid] = 0.f;
        g_cf[n * HH + tid] = 0.f;
        g_cb[n * HH + tid] = 0.f;
    }
    g_pin[n * DD + tid] = 0.f;     // tid covers 0..255
}

// ---------------- embedding: embT[t][b][e] = inputs[b][t][:] . W_embed[e][:] --
__global__ void embed_kernel(const float* __restrict__ inp, const float* __restrict__ We) {
    int idx = blockIdx.x * 256 + threadIdx.x;   // total = TT*BN*EE = 6,553,600 exactly
    int e = idx & 127;
    int b = (idx >> 7) & 511;
    int t = idx >> 16;
    float x0 = inp[(b * TT + t) * 2 + 0];
    float x1 = inp[(b * TT + t) * 2 + 1];
    g_embT[(t * BN + b) * EE + e] = x0 * We[e * 2 + 0] + x1 * We[e * 2 + 1];
}

// ---------------- fused LSTM-step tile: GEMM + gate nonlinearity --------------
// Block computes 32 batch rows x 32 hidden cols, gathered across ALL 4 gate
// groups (columns g*128 + j); epilogue applies the full LSTM cell update.
// gates = [x | hprev] @ W.T + bias.
template <int KXW>
__device__ __forceinline__ void lstm_tile(
    const float* __restrict__ x,      // [BN][KXW]
    const float* __restrict__ hprev,  // [BN][128]
    const float* __restrict__ W,      // [512][KXW+128] packed
    const float* __restrict__ bias,   // [512] (i,f,g,o blocks of 128)
    float* __restrict__ c,            // [BN][128] in-place
    float* __restrict__ hnext,        // [BN][128]
    float* __restrict__ out2,         // secondary h write (enc slot or pout)
    int out2_stride, int out2_col0)
{
    constexpr int KT = KXW + 128;
    constexpr int NC = KT / 32;
    __shared__ __align__(16) float sA[32][36];      // sA[k][m]
    __shared__ __align__(16) float sW[128][33];     // sW[g*32+jj][k]

    int tid = threadIdx.x;
    int jj = tid & 31;                // hidden col within tile
    int my = tid >> 5;                // warp id -> 4-row group
    int m0 = blockIdx.x * 32;
    int j0 = blockIdx.y * 32;

    float acc[4][4];                  // [row r][gate g]
#pragma unroll
    for (int r = 0; r < 4; r++)
#pragma unroll
        for (int g = 0; g < 4; g++) acc[r][g] = 0.f;

    int arow = tid >> 3;              // 0..31
    int akq  = (tid & 7) * 4;         // 0,4,...,28
    int wr   = tid >> 1;              // 0..127 gathered weight row
    int wn   = ((wr >> 5) * 128) + j0 + (wr & 31);
    int wkh  = (tid & 1) * 16;

#pragma unroll 1
    for (int cc0 = 0; cc0 < NC; cc0++) {
        int k0 = cc0 * 32;
        const float* src; int ldx; int cb;
        if (k0 < KXW) { src = x;     ldx = KXW; cb = k0;       }
        else          { src = hprev; ldx = 128; cb = k0 - KXW; }
        float4 av = *reinterpret_cast<const float4*>(src + (m0 + arow) * ldx + cb + akq);
        const float* wp = W + wn * KT + k0 + wkh;
        float4 w0 = *reinterpret_cast<const float4*>(wp + 0);
        float4 w1 = *reinterpret_cast<const float4*>(wp + 4);
        float4 w2 = *reinterpret_cast<const float4*>(wp + 8);
        float4 w3 = *reinterpret_cast<const float4*>(wp + 12);

        sA[akq + 0][arow] = av.x; sA[akq + 1][arow] = av.y;
        sA[akq + 2][arow] = av.z; sA[akq + 3][arow] = av.w;
        sW[wr][wkh + 0]  = w0.x; sW[wr][wkh + 1]  = w0.y;
        sW[wr][wkh + 2]  = w0.z; sW[wr][wkh + 3]  = w0.w;
        sW[wr][wkh + 4]  = w1.x; sW[wr][wkh + 5]  = w1.y;
        sW[wr][wkh + 6]  = w1.z; sW[wr][wkh + 7]  = w1.w;
        sW[wr][wkh + 8]  = w2.x; sW[wr][wkh + 9]  = w2.y;
        sW[wr][wkh + 10] = w2.z; sW[wr][wkh + 11] = w2.w;
        sW[wr][wkh + 12] = w3.x; sW[wr][wkh + 13] = w3.y;
        sW[wr][wkh + 14] = w3.z; sW[wr][wkh + 15] = w3.w;
        __syncthreads();

#pragma unroll
        for (int k = 0; k < 32; k++) {
            float4 a = *reinterpret_cast<const float4*>(&sA[k][my * 4]);  // broadcast
            float wi = sW[      jj][k];
            float wf = sW[ 32 + jj][k];
            float wg = sW[ 64 + jj][k];
            float wo = sW[ 96 + jj][k];
            acc[0][0] += a.x * wi; acc[0][1] += a.x * wf; acc[0][2] += a.x * wg; acc[0][3] += a.x * wo;
            acc[1][0] += a.y * wi; acc[1][1] += a.y * wf; acc[1][2] += a.y * wg; acc[1][3] += a.y * wo;
            acc[2][0] += a.z * wi; acc[2][1] += a.z * wf; acc[2][2] += a.z * wg; acc[2][3] += a.z * wo;
            acc[3][0] += a.w * wi; acc[3][1] += a.w * wf; acc[3][2] += a.w * wg; acc[3][3] += a.w * wo;
        }
        __syncthreads();
    }

    // epilogue: LSTM cell update (PyTorch gate order i,f,g,o)
    int j = j0 + jj;
    float bi = bias[j], bf = bias[128 + j], bg = bias[256 + j], bo = bias[384 + j];
#pragma unroll
    for (int r = 0; r < 4; r++) {
        int m = m0 + my * 4 + r;
        float ig = acc[r][0] + bi;
        float fg = acc[r][1] + bf;
        float gg = acc[r][2] + bg;
        float og = acc[r][3] + bo;
        float cold = c[m * HH + j];
        float cn = fsig(fg) * cold + fsig(ig) * ftanh(gg);
        float hn = fsig(og) * ftanh(cn);
        c[m * HH + j]     = cn;
        hnext[m * HH + j] = hn;
        out2[m * out2_stride + out2_col0 + j] = hn;
    }
}

// encoder step t: blockIdx.z = direction (0 fwd, 1 bwd)
__global__ void __launch_bounds__(256) enc_step_kernel(int t,
        const float* __restrict__ bfv, const float* __restrict__ bbv) {
    int dir = blockIdx.z;
    int tt  = dir ? (TT - 1 - t) : t;
    int par = t & 1;
    const float* x     = g_embT + tt * BN * EE;
    float*       hbase = dir ? g_hb : g_hf;
    const float* hprev = hbase + par * BN * HH;
    float*       hnext = hbase + (par ^ 1) * BN * HH;
    float*       c     = dir ? g_cb : g_cf;
    const float* W     = dir ? g_Web : g_Wef;
    const float* bias  = dir ? bbv : bfv;
    lstm_tile<128>(x, hprev, W, bias, c, hnext, g_enc, TT * DD, tt * DD + dir * HH);
}

// process-loop cell, iteration it: blockIdx.z = direction
// parity lines up: encoder final h lands at parity 0; proc it=0 reads parity 0.
__global__ void __launch_bounds__(256) proc_cell_kernel(int it,
        const float* __restrict__ bfv, const float* __restrict__ bbv) {
    int dir = blockIdx.z;
    int par = it & 1;
    float*       hbase = dir ? g_hb : g_hf;
    const float* hprev = hbase + par * BN * HH;
    float*       hnext = hbase + (par ^ 1) * BN * HH;
    float*       c     = dir ? g_cb : g_cf;
    const float* W     = dir ? g_Wpb : g_Wpf;
    const float* bias  = dir ? bbv : bfv;
    lstm_tile<256>(g_pin, hprev, W, bias, c, hnext, g_pout, DD, dir * HH);
}

// ---------------- plain GEMM: C[m][n] = sum_k A[m][k] * Wt[n][k], K = N = 256 -
// MODE 0: A = g_enc  -> C = g_ref   (M = BN*TT)
// MODE 1: A = g_pout -> C = g_q     (M = BN)
template <int MODE>
__global__ void __launch_bounds__(256) gemm256_kernel(const float* __restrict__ Wt) {
    const float* A = (MODE == 0) ? g_enc : g_pout;
    float*       C = (MODE == 0) ? g_ref : g_q;
    __shared__ __align__(16) float sA[16][68];
    __shared__ __align__(16) float sB[16][68];
    int tid = threadIdx.x;
    int tx = tid & 15, ty = tid >> 4;
    int m0 = blockIdx.x * 64, n0 = blockIdx.y * 64;
    float acc[4][4] = {};
    int lrow = tid >> 2;        // 0..63
    int lk   = (tid & 3) * 4;   // 0,4,8,12
#pragma unroll 1
    for (int k0 = 0; k0 < 256; k0 += 16) {
        float4 a = *reinterpret_cast<const float4*>(A  + (m0 + lrow) * 256 + k0 + lk);
        float4 b = *reinterpret_cast<const float4*>(Wt + (n0 + lrow) * 256 + k0 + lk);
        sA[lk + 0][lrow] = a.x; sA[lk + 1][lrow] = a.y; sA[lk + 2][lrow] = a.z; sA[lk + 3][lrow] = a.w;
        sB[lk + 0][lrow] = b.x; sB[lk + 1][lrow] = b.y; sB[lk + 2][lrow] = b.z; sB[lk + 3][lrow] = b.w;
        __syncthreads();
#pragma unroll
        for (int k = 0; k < 16; k++) {
            float4 av = *reinterpret_cast<const float4*>(&sA[k][ty * 4]);
            float4 bv = *reinterpret_cast<const float4*>(&sB[k][tx * 4]);
            acc[0][0] += av.x * bv.x; acc[0][1] += av.x * bv.y; acc[0][2] += av.x * bv.z; acc[0][3] += av.x * bv.w;
            acc[1][0] += av.y * bv.x; acc[1][1] += av.y * bv.y; acc[1][2] += av.y * bv.z; acc[1][3] += av.y * bv.w;
            acc[2][0] += av.z * bv.x; acc[2][1] += av.z * bv.y; acc[2][2] += av.z * bv.z; acc[2][3] += av.z * bv.w;
            acc[3][0] += av.w * bv.x; acc[3][1] += av.w * bv.y; acc[3][2] += av.w * bv.z; acc[3][3] += av.w * bv.w;
        }
        __syncthreads();
    }
#pragma unroll
    for (int r = 0; r < 4; r++) {
        float4 o = make_float4(acc[r][0], acc[r][1], acc[r][2], acc[r][3]);
        *reinterpret_cast<float4*>(C + (m0 + ty * 4 + r) * 256 + n0 + tx * 4) = o;
    }
}

// ---------------- attention: scores -> softmax -> glimpse ---------------------
// block = batch element; v_b dropped (softmax shift-invariant)
__global__ void __launch_bounds__(256) att_kernel(const float* __restrict__ vw) {
    int b = blockIdx.x;
    int tid = threadIdx.x, lane = tid & 31, w = tid >> 5;
    __shared__ float sq[DD], sv[DD], sc[128];
    __shared__ float s_inv;
    sq[tid] = g_q[b * DD + tid];
    sv[tid] = vw[tid];
    __syncthreads();

    // scores: warp per t
    for (int t = w; t < TT; t += 8) {
        const float* rr = g_ref + (b * TT + t) * DD;
        float s = 0.f;
#pragma unroll
        for (int u = 0; u < 8; u++) {
            int d = lane + u * 32;
            s += sv[d] * ftanh(rr[d] + sq[d]);
        }
#pragma unroll
        for (int o = 16; o; o >>= 1) s += __shfl_xor_sync(0xffffffffu, s, o);
        if (lane == 0) sc[t] = s;
    }
    __syncthreads();

    // softmax (warp 0), leaves exp values in sc and 1/sum in s_inv
    if (tid < 32) {
        float v0 = (tid      < TT) ? sc[tid]      : -1e30f;
        float v1 = (tid + 32 < TT) ? sc[tid + 32] : -1e30f;
        float v2 = (tid + 64 < TT) ? sc[tid + 64] : -1e30f;
        float v3 = (tid + 96 < TT) ? sc[tid + 96] : -1e30f;
        float mx = fmaxf(fmaxf(v0, v1), fmaxf(v2, v3));
#pragma unroll
        for (int o = 16; o; o >>= 1) mx = fmaxf(mx, __shfl_xor_sync(0xffffffffu, mx, o));
        float e0 = (tid      < TT) ? __expf(v0 - mx) : 0.f;
        float e1 = (tid + 32 < TT) ? __expf(v1 - mx) : 0.f;
        float e2 = (tid + 64 < TT) ? __expf(v2 - mx) : 0.f;
        float e3 = (tid + 96 < TT) ? __expf(v3 - mx) : 0.f;
        if (tid      < TT) sc[tid]      = e0;
        if (tid + 32 < TT) sc[tid + 32] = e1;
        if (tid + 64 < TT) sc[tid + 64] = e2;
        if (tid + 96 < TT) sc[tid + 96] = e3;
        float sum = e0 + e1 + e2 + e3;
#pragma unroll
        for (int o = 16; o; o >>= 1) sum += __shfl_xor_sync(0xffffffffu, sum, o);
        if (tid == 0) s_inv = __fdividef(1.f, sum);
    }
    __syncthreads();

    // glimpse: pin[b][d] = (sum_t e_t * enc[b][t][d]) * inv
    float acc = 0.f;
    const float* er = g_enc + b * TT * DD + tid;
#pragma unroll 4
    for (int t = 0; t < TT; t++) acc += sc[t] * er[t * DD];
    g_pin[b * DD + tid] = acc * s_inv;
}

// ---------------- final MLP head: out[b] = relu(pout@W1.T+b1)@W2.T + b2 ------
__global__ void __launch_bounds__(256) head_kernel(
        const float* __restrict__ W1, const float* __restrict__ b1,
        const float* __restrict__ W2, const float* __restrict__ b2,
        float* __restrict__ out) {
    int b = blockIdx.x;
    int tid = threadIdx.x, lane = tid & 31, w = tid >> 5;
    __shared__ float sp[DD];
    __shared__ float sh[8];
    sp[tid] = g_pout[b * DD + tid];
    __syncthreads();
    float hv = 0.f;
    if (tid < 100) {   // MID = 100 hidden units
        const float* wr = W1 + tid * DD;
        float s = 0.f;
#pragma unroll 8
        for (int k = 0; k < DD; k++) s += sp[k] * wr[k];
        hv = fmaxf(s + b1[tid], 0.f) * W2[tid];
    }
#pragma unroll
    for (int o = 16; o; o >>= 1) hv += __shfl_xor_sync(0xffffffffu, hv, o);
    if (lane == 0) sh[w] = hv;
    __syncthreads();
    if (tid == 0) {
        float s = 0.f;
#pragma unroll
        for (int i = 0; i < 8; i++) s += sh[i];
        out[b] = s + b2[0];
    }
}

// ---------------- launch ------------------------------------------------------
extern "C" void kernel_launch(void* const* d_in, const int* in_sizes, int n_in,
                              void* d_out, int out_size) {
    (void)in_sizes; (void)n_in; (void)out_size;
    const float* inputs   = (const float*)d_in[0];
    const float* W_embed  = (const float*)d_in[1];
    const float* enc_b_f  = (const float*)d_in[4];
    const float* enc_b_b  = (const float*)d_in[7];
    const float* W_ref    = (const float*)d_in[8];
    const float* W_q      = (const float*)d_in[9];
    const float* v_w      = (const float*)d_in[10];
    const float* proc_b_f = (const float*)d_in[14];
    const float* proc_b_b = (const float*)d_in[17];
    const float* W1       = (const float*)d_in[18];
    const float* b1       = (const float*)d_in[19];
    const float* W2       = (const float*)d_in[20];
    const float* b2       = (const float*)d_in[21];
    float* out = (float*)d_out;

    pack_kernel<<<512, 256>>>((const float*)d_in[2],  (const float*)d_in[3],
                              (const float*)d_in[5],  (const float*)d_in[6],
                              (const float*)d_in[12], (const float*)d_in[13],
                              (const float*)d_in[15], (const float*)d_in[16]);
    embed_kernel<<<(TT * BN * EE) / 256, 256>>>(inputs, W_embed);

    for (int t = 0; t < TT; t++)
        enc_step_kernel<<<dim3(BN / 32, HH / 32, 2), 256>>>(t, enc_b_f, enc_b_b);

    gemm256_kernel<0><<<dim3((BN * TT) / 64, DD / 64), 256>>>(W_ref);

    for (int it = 0; it < TT; it++) {
        proc_cell_kernel<<<dim3(BN / 32, HH / 32, 2), 256>>>(it, proc_b_f, proc_b_b);
        if (it < TT - 1) {
            gemm256_kernel<1><<<dim3(BN / 64, DD / 64), 256>>>(W_q);
            att_kernel<<<BN, 256>>>(v_w);
        }
    }

    head_kernel<<<BN, 256>>>(W1, b1, W2, b2, out);
}